// round 16
// baseline (speedup 1.0000x reference)
#include <cuda_runtime.h>

// DWT1D bior3.5, J=3, fused. R15 = R14 (fully unrolled head/middle/tail,
// packed fma.rn.f32x2, conflict-free plain smem, 4 CTAs/SM) plus:
//  - first tap uses mul.rn.f32x2 (kills 8 zero-init MOVs per group,
//    bitwise-identical results)
//  - hi2 stored with unconditional STG.64 (base row*4104 is always aligned)
//  - hi1/hi3/x0 stored with warp-uniform alignment-checked STG.64
//    (aligned on even rows; scalar pair otherwise)
//
// lo[n] = sum_l s[2n-10+l]*h0[l]  (zero extension; odd-pad == zero extension)
// h1[i] = (i even ? -1 : +1) * h0[11-i]
// Output: [x0(=lo3) | hi1 | hi2 | hi3], rows concatenated per section.

#define N_IN   16384
#define O1     8197
#define O2     4104
#define O3     2057
#define NROWS  1024
#define BD     256

#define SL1_F  8208      // valid [0,8197), zeros [8197,8208)
#define SL2_F  4116      // valid [0,4104), zeros [4104,4116)
#define SMEM_FLOATS (SL1_F + SL2_F)          // 12324 floats = 49296 B

#define OFF_X0  0
#define OFF_H1  ((size_t)NROWS * O3)
#define OFF_H2  (OFF_H1 + (size_t)NROWS * O1)
#define OFF_H3  (OFF_H2 + (size_t)NROWS * O2)

typedef unsigned long long u64;

__device__ __forceinline__ u64 ffma2(u64 a, u64 b, u64 c) {
    u64 d;
    asm("fma.rn.f32x2 %0, %1, %2, %3;" : "=l"(d) : "l"(a), "l"(b), "l"(c));
    return d;
}
__device__ __forceinline__ u64 fmul2(u64 a, u64 b) {
    u64 d;
    asm("mul.rn.f32x2 %0, %1, %2;" : "=l"(d) : "l"(a), "l"(b));
    return d;
}
__device__ __forceinline__ u64 pack2(float x, float y) {
    u64 r;
    asm("mov.b64 %0, {%1, %2};" : "=l"(r) : "f"(x), "f"(y));
    return r;
}
__device__ __forceinline__ void unpack2(u64 a, float& x, float& y) {
    asm("mov.b64 {%0, %1}, %2;" : "=f"(x), "=f"(y) : "l"(a));
}
__device__ __forceinline__ float hsum2(u64 a) {
    float x, y;
    unpack2(a, x, y);
    return x + y;
}

// Warp-uniform alignment-checked pair store (base alignment is per-row,
// offsets are even -> predicate uniform across the warp and the level).
__device__ __forceinline__ void store2u(float* p, float a, float b, bool al) {
    if (al) *(float2*)p = make_float2(a, b);
    else { p[0] = a; p[1] = b; }
}

// 8 natural even pairs covering src[4t-12 .. 4t+3] (16B lane stride).
struct VP { u64 v[8]; };

__device__ __forceinline__ void load_vp(const ulonglong2* __restrict__ s2,
                                        int t, VP& w) {
    #pragma unroll
    for (int q = 0; q < 4; q++) {
        ulonglong2 a = s2[t - 3 + q];
        w.v[2 * q]     = a.x;
        w.v[2 * q + 1] = a.y;
    }
}

__device__ __forceinline__ void compute_vp(const VP& w,
                                           const u64* __restrict__ ch0,
                                           const u64* __restrict__ ch1,
                                           float& lo0, float& lo1,
                                           float& hi0, float& hi1) {
    // First tap as mul (0-init folded away; rounds identically to 0 + x*y).
    u64 a0 = fmul2(w.v[1], ch0[0]);
    u64 b0 = fmul2(w.v[1], ch1[0]);
    u64 a1 = fmul2(w.v[2], ch0[0]);
    u64 b1 = fmul2(w.v[2], ch1[0]);
    #pragma unroll
    for (int m = 1; m < 6; m++) {
        a0 = ffma2(w.v[1 + m], ch0[m], a0);
        b0 = ffma2(w.v[1 + m], ch1[m], b0);
        a1 = ffma2(w.v[2 + m], ch0[m], a1);
        b1 = ffma2(w.v[2 + m], ch1[m], b1);
    }
    lo0 = hsum2(a0); hi0 = hsum2(b0);
    lo1 = hsum2(a1); hi1 = hsum2(b1);
}

// Edge path: zero extension via masked scalar taps.
__device__ __forceinline__ void compute_edge(const float* __restrict__ src,
                                             int src_valid, int t,
                                             const u64* __restrict__ ch0,
                                             const u64* __restrict__ ch1,
                                             float& lo0, float& lo1,
                                             float& hi0, float& hi1) {
    float h0s[12], h1s[12];
    #pragma unroll
    for (int m = 0; m < 6; m++) {
        unpack2(ch0[m], h0s[2 * m], h0s[2 * m + 1]);
        unpack2(ch1[m], h1s[2 * m], h1s[2 * m + 1]);
    }
    float lv[2] = {0.f, 0.f}, hv[2] = {0.f, 0.f};
    #pragma unroll
    for (int j = 0; j < 2; j++) {
        const int n = 2 * t + j;
        #pragma unroll
        for (int l = 0; l < 12; l++) {
            const int idx = 2 * n - 10 + l;
            if (idx >= 0 && idx < src_valid) {
                const float xv = src[idx];
                lv[j] += xv * h0s[l];
                hv[j] += xv * h1s[l];
            }
        }
    }
    lo0 = lv[0]; hi0 = hv[0]; lo1 = lv[1]; hi1 = hv[1];
}

// Unconditional emit (head/middle groups: provably n0+1 < M).
__device__ __forceinline__ void emit_full(int t,
                                          float lo0, float lo1,
                                          float hi0, float hi1,
                                          float* __restrict__ lo_smem,
                                          float* __restrict__ lo_gmem,
                                          float* __restrict__ hi_gmem,
                                          bool hi_al, bool lo_al) {
    const int n0 = 2 * t;
    if (lo_smem) ((float2*)lo_smem)[t] = make_float2(lo0, lo1);
    store2u(hi_gmem + n0, hi0, hi1, hi_al);
    if (lo_gmem) store2u(lo_gmem + n0, lo0, lo1, lo_al);
}

// One level, fully unrolled. G = total groups, NMID = provably-fast middle
// iterations (i=1..NMID), TAIL_FAST = tail groups may use the vector path.
template<int M, int G, int NMID, bool TAIL_FAST>
__device__ __forceinline__ void run_level(
    const float* __restrict__ src, int src_valid,
    const u64* __restrict__ ch0, const u64* __restrict__ ch1,
    float* __restrict__ lo_smem,     // nullable (compile-time)
    float* __restrict__ lo_gmem,     // nullable (compile-time)
    float* __restrict__ hi_gmem)
{
    const ulonglong2* s2 = (const ulonglong2*)src;
    const int tid = threadIdx.x;
    const bool hi_al = ((((size_t)hi_gmem) & 7) == 0);
    const bool lo_al = lo_gmem ? ((((size_t)lo_gmem) & 7) == 0) : false;

    // head (i = 0): only threads t<3 diverge into the edge path.
    {
        const int t = tid;
        float lo0, lo1, hi0, hi1;
        if (t >= 3) {
            VP w; load_vp(s2, t, w);
            compute_vp(w, ch0, ch1, lo0, lo1, hi0, hi1);
        } else {
            compute_edge(src, src_valid, t, ch0, ch1, lo0, lo1, hi0, hi1);
        }
        emit_full(t, lo0, lo1, hi0, hi1, lo_smem, lo_gmem, hi_gmem, hi_al, lo_al);
    }

    // middle: pure fast path, no predicates, immediate-offset addresses.
    #pragma unroll
    for (int i = 1; i <= NMID; i++) {
        const int t = tid + i * BD;
        VP w; load_vp(s2, t, w);
        float lo0, lo1, hi0, hi1;
        compute_vp(w, ch0, ch1, lo0, lo1, hi0, hi1);
        emit_full(t, lo0, lo1, hi0, hi1, lo_smem, lo_gmem, hi_gmem, hi_al, lo_al);
    }

    // tail: few threads, checked emit (scalar stores; negligible).
    {
        const int t = tid + (NMID + 1) * BD;
        if (t < G) {
            float lo0, lo1, hi0, hi1;
            if (TAIL_FAST) {
                VP w; load_vp(s2, t, w);
                compute_vp(w, ch0, ch1, lo0, lo1, hi0, hi1);
            } else {
                compute_edge(src, src_valid, t, ch0, ch1, lo0, lo1, hi0, hi1);
            }
            const int n0 = 2 * t;
            const bool ok1 = (n0 + 1 < M);
            if (lo_smem) {
                if (ok1) ((float2*)lo_smem)[t] = make_float2(lo0, lo1);
                else     lo_smem[n0] = lo0;     // pads beyond M stay zero
            }
            hi_gmem[n0] = hi0;
            if (lo_gmem) lo_gmem[n0] = lo0;
            if (ok1) {
                hi_gmem[n0 + 1] = hi1;
                if (lo_gmem) lo_gmem[n0 + 1] = lo1;
            }
        }
    }
}

__global__ void __launch_bounds__(BD, 4)
dwt1d_r15_kernel(const float* __restrict__ x,
                 const float* __restrict__ hac,
                 float* __restrict__ out)
{
    extern __shared__ float sm[];
    float* sl1 = sm;
    float* sl2 = sm + SL1_F;

    const int row = blockIdx.x;
    const float* xr = x + (size_t)row * N_IN;

    // Packed coefficient pairs: ch0[m]=(h0[2m],h0[2m+1]), ch1 likewise for h1.
    u64 ch0[6], ch1[6];
    {
        float h0s[12], h1s[12];
        #pragma unroll
        for (int i = 0; i < 12; i++) h0s[i] = __ldg(hac + i);
        #pragma unroll
        for (int i = 0; i < 12; i++)
            h1s[i] = ((i & 1) ? 1.0f : -1.0f) * h0s[11 - i];
        #pragma unroll
        for (int m = 0; m < 6; m++) {
            ch0[m] = pack2(h0s[2 * m], h0s[2 * m + 1]);
            ch1[m] = pack2(h1s[2 * m], h1s[2 * m + 1]);
        }
    }

    // Zero pads (zero-extension for the next level's fast path; never
    // overwritten: levels store only n < M into smem).
    if (threadIdx.x < 11)       sl1[O1 + threadIdx.x] = 0.f;        // 8197..8207
    else if (threadIdx.x < 23)  sl2[O2 + (threadIdx.x - 11)] = 0.f; // 4104..4115

    float* hi1 = out + OFF_H1 + (size_t)row * O1;
    float* hi2 = out + OFF_H2 + (size_t)row * O2;
    float* hi3 = out + OFF_H3 + (size_t)row * O3;
    float* x0  = out + OFF_X0 + (size_t)row * O3;

    // Level 1: gmem -> (sl1, hi1). G=4099, middle i=1..15 (t<=4095: max read
    // 4*4095+3 = 16383 ✓); tail t=4096..4098 is the right zero-extension edge.
    run_level<O1, 4099, 15, false>(xr, N_IN, ch0, ch1, sl1, nullptr, hi1);
    __syncthreads();
    // Level 2: sl1 -> (sl2, hi2). G=2052, middle i=1..7 (t<=2047); tail
    // t=2048..2051 fast (max read 4*2051+3 = 8207 < 8208).
    run_level<O2, 2052, 7, true>(sl1, SL1_F, ch0, ch1, sl2, nullptr, hi2);
    __syncthreads();
    // Level 3: sl2 -> (x0, hi3). G=1029, middle i=1..3 (t<=1023); tail
    // t=1024..1028 fast (max read 4*1028+3 = 4115 < 4116).
    run_level<O3, 1029, 3, true>(sl2, SL2_F, ch0, ch1, nullptr, x0, hi3);
}

extern "C" void kernel_launch(void* const* d_in, const int* in_sizes, int n_in,
                              void* d_out, int out_size)
{
    int xi = 0, hi = 1;
    if (n_in >= 2 && in_sizes[0] == 12) { xi = 1; hi = 0; }

    const float* x   = (const float*)d_in[xi];
    const float* hac = (const float*)d_in[hi];
    float* out = (float*)d_out;

    const size_t smem_bytes = (size_t)SMEM_FLOATS * sizeof(float);   // 49296
    cudaFuncSetAttribute(dwt1d_r15_kernel,
                         cudaFuncAttributeMaxDynamicSharedMemorySize,
                         (int)smem_bytes);
    cudaFuncSetAttribute(dwt1d_r15_kernel,
                         cudaFuncAttributePreferredSharedMemoryCarveout, 100);

    dwt1d_r15_kernel<<<NROWS, BD, smem_bytes>>>(x, hac, out);
}

// round 17
// speedup vs baseline: 1.1039x; 1.1039x over previous
#include <cuda_runtime.h>

// DWT1D bior3.5, J=3, fused. R16 = R14 core (packed 2-output loads,
// fma.rn.f32x2, zero-init accumulators, conflict-free plain smem, fully
// unrolled compile-time head/middle/tail) with each row split into TWO
// half-row CTAs (halo recompute). smem/CTA 24.8KB + launch_bounds(256,5)
// -> 5 CTAs/SM = 40 warps (was 32; both regfile- and smem-capped before).
//
// lo[n] = sum_l s[2n-10+l]*h0[l]  (zero extension; odd-pad == zero extension)
// h1[i] = (i even ? -1 : +1) * h0[11-i]
// Output: [x0(=lo3) | hi1 | hi2 | hi3], rows concatenated per section.
//
// Half ranges (group t computes outputs n=2t,2t+1 at each level):
//            level1 t        level2 t        level3 t
//   half0:   [0,2059)        [0,1029)        [0,514)      (left edges t<3)
//   half1:   [2038,4099)     [1022,2052)     [514,1029)   (right edge t>=4096 in L1)
// half1 smem origins: lo1 floats@4076 (slot t-2038), lo2 floats@2044 (slot t-1022).
// Halo (computed but hi not stored): L1 t<2059, L2 t<1029 -> i==0 predicate only.

#define N_IN   16384
#define O1     8197
#define O2     4104
#define O3     2057
#define NROWS  1024
#define BD     256

#define SL1_F  4136     // half1: valid local [0,4122), zeros [4122,4136)
#define SL2_F  2072     // half1: valid local [0,2060), zeros [2060,2072)
#define SMEM_FLOATS (SL1_F + SL2_F)   // 6208 floats = 24832 B

#define OFF_X0  0
#define OFF_H1  ((size_t)NROWS * O3)
#define OFF_H2  (OFF_H1 + (size_t)NROWS * O1)
#define OFF_H3  (OFF_H2 + (size_t)NROWS * O2)

typedef unsigned long long u64;

__device__ __forceinline__ u64 ffma2(u64 a, u64 b, u64 c) {
    u64 d;
    asm("fma.rn.f32x2 %0, %1, %2, %3;" : "=l"(d) : "l"(a), "l"(b), "l"(c));
    return d;
}
__device__ __forceinline__ u64 pack2(float x, float y) {
    u64 r;
    asm("mov.b64 %0, {%1, %2};" : "=l"(r) : "f"(x), "f"(y));
    return r;
}
__device__ __forceinline__ void unpack2(u64 a, float& x, float& y) {
    asm("mov.b64 {%0, %1}, %2;" : "=f"(x), "=f"(y) : "l"(a));
}
__device__ __forceinline__ float hsum2(u64 a) {
    float x, y;
    unpack2(a, x, y);
    return x + y;
}

// 8 natural even pairs covering src units [tu-3, tu] (16B lane stride).
struct VP { u64 v[8]; };

__device__ __forceinline__ void load_vp(const ulonglong2* __restrict__ s2,
                                        int tu, VP& w) {
    #pragma unroll
    for (int q = 0; q < 4; q++) {
        ulonglong2 a = s2[tu - 3 + q];
        w.v[2 * q]     = a.x;
        w.v[2 * q + 1] = a.y;
    }
}

__device__ __forceinline__ void compute_vp(const VP& w,
                                           const u64* __restrict__ ch0,
                                           const u64* __restrict__ ch1,
                                           float& lo0, float& lo1,
                                           float& hi0, float& hi1) {
    u64 a0 = 0ull, b0 = 0ull, a1 = 0ull, b1 = 0ull;
    #pragma unroll
    for (int m = 0; m < 6; m++) {
        a0 = ffma2(w.v[1 + m], ch0[m], a0);
        b0 = ffma2(w.v[1 + m], ch1[m], b0);
        a1 = ffma2(w.v[2 + m], ch0[m], a1);
        b1 = ffma2(w.v[2 + m], ch1[m], b1);
    }
    lo0 = hsum2(a0); hi0 = hsum2(b0);
    lo1 = hsum2(a1); hi1 = hsum2(b1);
}

// Edge path: zero extension via masked scalar taps. All edge call sites have
// src float-origin 0 (x rows, or half0 smem arrays), global indexing.
__device__ __forceinline__ void compute_edge(const float* __restrict__ src,
                                             int src_valid, int t,
                                             const u64* __restrict__ ch0,
                                             const u64* __restrict__ ch1,
                                             float& lo0, float& lo1,
                                             float& hi0, float& hi1) {
    float h0s[12], h1s[12];
    #pragma unroll
    for (int m = 0; m < 6; m++) {
        unpack2(ch0[m], h0s[2 * m], h0s[2 * m + 1]);
        unpack2(ch1[m], h1s[2 * m], h1s[2 * m + 1]);
    }
    float lv[2] = {0.f, 0.f}, hv[2] = {0.f, 0.f};
    #pragma unroll
    for (int j = 0; j < 2; j++) {
        const int n = 2 * t + j;
        #pragma unroll
        for (int l = 0; l < 12; l++) {
            const int idx = 2 * n - 10 + l;
            if (idx >= 0 && idx < src_valid) {
                const float xv = src[idx];
                lv[j] += xv * h0s[l];
                hv[j] += xv * h1s[l];
            }
        }
    }
    lo0 = lv[0]; hi0 = hv[0]; lo1 = lv[1]; hi1 = hv[1];
}

// Generic level, fully unrolled; all structure compile-time.
//  T_BEGIN..T_END : group range (t computes n = 2t, 2t+1)
//  SRC_U_ORG      : 16B-unit origin of src buffer (0 for gmem / half0 smem)
//  SLOT_ORG       : lo smem float2 slot = t - SLOT_ORG
//  EDGE_LO        : t < EDGE_LO  -> edge path (only possible at i==0)
//  EDGE_HI        : t >= EDGE_HI -> edge path (only possible at last i)
//  HI_T_MIN       : store hi only for t >= HI_T_MIN (halo skip; i==0 only)
//  N_LIMIT        : second output stored only if 2t+1 < N_LIMIT
template<int T_BEGIN, int T_END, int SRC_U_ORG, int SLOT_ORG,
         int EDGE_LO, int EDGE_HI, int HI_T_MIN, int N_LIMIT,
         bool HAS_LO_SMEM, bool HAS_LO_GMEM>
__device__ __forceinline__ void run_level(
    const float* __restrict__ src, int src_valid,
    const u64* __restrict__ ch0, const u64* __restrict__ ch1,
    float* __restrict__ lo_smem,
    float* __restrict__ lo_gmem,
    float* __restrict__ hi_gmem)
{
    constexpr int NI = (T_END - T_BEGIN + BD - 1) / BD;
    const ulonglong2* s2 = (const ulonglong2*)src;
    const int tid = threadIdx.x;

    #pragma unroll
    for (int i = 0; i < NI; i++) {
        const int t = T_BEGIN + tid + i * BD;
        if (i == NI - 1 && ((T_END - T_BEGIN) % BD) != 0) {
            if (t >= T_END) break;
        }

        bool fast = true;
        if (i == 0 && EDGE_LO > T_BEGIN)      fast = (t >= EDGE_LO);
        if (i == NI - 1 && EDGE_HI < T_END)   fast = fast && (t < EDGE_HI);

        float lo0, lo1, hi0, hi1;
        if (fast) {
            VP w; load_vp(s2, t - SRC_U_ORG, w);
            compute_vp(w, ch0, ch1, lo0, lo1, hi0, hi1);
        } else {
            compute_edge(src, src_valid, t, ch0, ch1, lo0, lo1, hi0, hi1);
        }

        // lo -> smem: unconditional pair (phantom slots hold exact zeros).
        if (HAS_LO_SMEM)
            ((float2*)lo_smem)[t - SLOT_ORG] = make_float2(lo0, lo1);

        const int n0 = 2 * t;
        bool do_hi = true;
        if (i == 0 && HI_T_MIN > T_BEGIN) do_hi = (t >= HI_T_MIN);
        bool ok1 = true;
        if (i == NI - 1 && (2 * (T_END - 1) + 1) >= N_LIMIT)
            ok1 = (n0 + 1 < N_LIMIT);

        if (do_hi) {
            hi_gmem[n0] = hi0;
            if (ok1) hi_gmem[n0 + 1] = hi1;
        }
        if (HAS_LO_GMEM) {
            lo_gmem[n0] = lo0;
            if (ok1) lo_gmem[n0 + 1] = lo1;
        }
    }
}

__global__ void __launch_bounds__(BD, 5)
dwt1d_r16_kernel(const float* __restrict__ x,
                 const float* __restrict__ hac,
                 float* __restrict__ out)
{
    extern __shared__ float sm[];
    float* sl1 = sm;
    float* sl2 = sm + SL1_F;

    const int half = blockIdx.x & 1;
    const int row  = blockIdx.x >> 1;
    const float* xr = x + (size_t)row * N_IN;

    // Packed coefficient pairs: ch0[m]=(h0[2m],h0[2m+1]), ch1 likewise for h1.
    u64 ch0[6], ch1[6];
    {
        float h0s[12], h1s[12];
        #pragma unroll
        for (int i = 0; i < 12; i++) h0s[i] = __ldg(hac + i);
        #pragma unroll
        for (int i = 0; i < 12; i++)
            h1s[i] = ((i & 1) ? 1.0f : -1.0f) * h0s[11 - i];
        #pragma unroll
        for (int m = 0; m < 6; m++) {
            ch0[m] = pack2(h0s[2 * m], h0s[2 * m + 1]);
            ch1[m] = pack2(h1s[2 * m], h1s[2 * m + 1]);
        }
    }

    // Zero the pad tails (only half1 reads them; harmless for half0). Written
    // before level 1; consumed after the first barrier. Never overwritten
    // (level stores stay below the pad regions).
    if (threadIdx.x < 14)       sl1[4122 + threadIdx.x] = 0.f;       // [4122,4136)
    else if (threadIdx.x < 26)  sl2[2060 + (threadIdx.x - 14)] = 0.f; // [2060,2072)

    float* hi1 = out + OFF_H1 + (size_t)row * O1;
    float* hi2 = out + OFF_H2 + (size_t)row * O2;
    float* hi3 = out + OFF_H3 + (size_t)row * O3;
    float* x0  = out + OFF_X0 + (size_t)row * O3;

    if (half == 0) {
        // L1: x -> (sl1@0, hi1[0,4118)). t in [0,2059); left edge t<3; all
        // fast reads <= float 4*2058+3 = 8235 < 16384.
        run_level<0, 2059, 0, 0, 3, 2059, 0, O1, true, false>(
            xr, N_IN, ch0, ch1, sl1, nullptr, hi1);
        __syncthreads();
        // L2: sl1 -> (sl2@0, hi2[0,2058)). t in [0,1029); reads <= 4115 < 4118.
        run_level<0, 1029, 0, 0, 3, 1029, 0, O2, true, false>(
            sl1, 4118, ch0, ch1, sl2, nullptr, hi2);
        __syncthreads();
        // L3: sl2 -> (x0, hi3)[0,1028). t in [0,514); reads <= 2055 < 2058.
        run_level<0, 514, 0, 0, 3, 514, 0, O3, false, true>(
            sl2, 2058, ch0, ch1, nullptr, x0, hi3);
    } else {
        // L1: x -> (sl1 slots t-2038 = lo1 floats@4076, hi1[4118,8197)).
        // t in [2038,4099); right edge t>=4096 (x reads would pass 16383);
        // halo t<2059 computes lo1 only. Phantom n=8197 is exact zero.
        run_level<2038, 4099, 0, 2038, 2038, 4096, 2059, O1, true, false>(
            xr, N_IN, ch0, ch1, sl1, nullptr, hi1);
        __syncthreads();
        // L2: sl1(@unit 1019) -> (sl2 slots t-1022 = lo2 floats@2044,
        // hi2[2058,4104)). t in [1022,2052); all fast: local reads
        // [0, 4131] < 4136 incl. zero pads (= lo1 zero-extension).
        run_level<1022, 2052, 1019, 1022, 1022, 2052, 1029, O2, true, false>(
            sl1, SL1_F, ch0, ch1, sl2, nullptr, hi2);
        __syncthreads();
        // L3: sl2(@unit 511) -> (x0, hi3)[1028,2057). t in [514,1029);
        // all fast: local reads [0, 2071] < 2072 incl. zero pads.
        run_level<514, 1029, 511, 514, 514, 1029, 514, O3, false, true>(
            sl2, SL2_F, ch0, ch1, nullptr, x0, hi3);
    }
}

extern "C" void kernel_launch(void* const* d_in, const int* in_sizes, int n_in,
                              void* d_out, int out_size)
{
    int xi = 0, hi = 1;
    if (n_in >= 2 && in_sizes[0] == 12) { xi = 1; hi = 0; }

    const float* x   = (const float*)d_in[xi];
    const float* hac = (const float*)d_in[hi];
    float* out = (float*)d_out;

    const size_t smem_bytes = (size_t)SMEM_FLOATS * sizeof(float);   // 24832
    cudaFuncSetAttribute(dwt1d_r16_kernel,
                         cudaFuncAttributeMaxDynamicSharedMemorySize,
                         (int)smem_bytes);
    cudaFuncSetAttribute(dwt1d_r16_kernel,
                         cudaFuncAttributePreferredSharedMemoryCarveout, 100);

    dwt1d_r16_kernel<<<2 * NROWS, BD, smem_bytes>>>(x, hac, out);
}